// round 11
// baseline (speedup 1.0000x reference)
#include <cuda_runtime.h>
#include <cstdint>

// sampling_map: [B=64, C=3, H=512, W=512] fp32 row-major.
// GRID=4 -> 128x128 cells; channel-sum; valid 3x3 window over 4x4 grid -> 2x2;
// argmax (TOP_K=1) -> coords (idx//2, idx%2), output [B,1,2] as FLOAT32.
// Mean factor 1/16384 is uniform -> argmax-invariant -> dropped.
static constexpr int B = 64;
static constexpr int C = 3;
static constexpr int H = 512;
static constexpr int W = 512;
static constexpr int GH = 128;
static constexpr int GW = 128;
static constexpr int W4 = W / 4;       // 128 float4 per image row

// Device-global scratch (zero-init, allocation-guard safe).
__device__ float        g_cells[B * 16];
__device__ unsigned int g_count[B];

// R9 winning structure: one block per (batch, cell), 1024 x 256,
// residency capped at 4 CTAs/SM (cuts cross-CTA L1tex-queue contention and
// lets ptxas batch loads deeply at 63 regs). __ldcs: zero-reuse stream.
__global__ __launch_bounds__(256, 4) void region_selector_kernel(
    const float* __restrict__ in, float* __restrict__ out) {
    const int blk  = blockIdx.x;
    const int cell = blk & 15;
    const int b    = blk >> 4;
    const int gy   = cell >> 2;
    const int gx   = cell & 3;

    const int t     = threadIdx.x;
    const int lane8 = t & 7;    // 8 threads cover one 128-float row (4 float4 ea)
    const int r0    = t >> 3;   // base row 0..31

    float acc = 0.0f;
#pragma unroll
    for (int c = 0; c < C; c++) {
        const float4* __restrict__ base = reinterpret_cast<const float4*>(in) +
            (((size_t)(b * C + c) * H) + (size_t)gy * GH) * W4 + gx * (GW / 4);
#pragma unroll
        for (int m = 0; m < 4; m++) {
            const float4* __restrict__ rowp = base + (size_t)(r0 + m * 32) * W4;
#pragma unroll
            for (int j = 0; j < 4; j++) {
                float4 v = __ldcs(&rowp[lane8 + j * 8]);   // evict-first stream
                acc += (v.x + v.y) + (v.z + v.w);
            }
        }
    }

    // Block reduction: warp shuffles, then 8 warps via smem.
    __shared__ float warp_sums[8];
#pragma unroll
    for (int off = 16; off > 0; off >>= 1)
        acc += __shfl_down_sync(0xFFFFFFFFu, acc, off);
    if ((t & 31) == 0) warp_sums[t >> 5] = acc;
    __syncthreads();

    if (t == 0) {
        float s = 0.0f;
#pragma unroll
        for (int w = 0; w < 8; w++) s += warp_sums[w];
        g_cells[blk] = s;
        __threadfence();                        // publish before the ticket
        const unsigned int done = atomicAdd(&g_count[b], 1u);
        if (done == 15u) {
            // Last finishing block of this batch: finalize.
            float cs[16];
#pragma unroll
            for (int k = 0; k < 16; k++)
                cs[k] = __ldcg(&g_cells[(b << 4) + k]);   // L2-coherent reads

            float ws[4];
#pragma unroll
            for (int i = 0; i < 2; i++) {
#pragma unroll
                for (int j = 0; j < 2; j++) {
                    float s2 = 0.0f;
#pragma unroll
                    for (int di = 0; di < 3; di++)
#pragma unroll
                        for (int dj = 0; dj < 3; dj++)
                            s2 += cs[(i + di) * 4 + (j + dj)];
                    ws[i * 2 + j] = s2;
                }
            }
            int best_idx = 0;
            float best = ws[0];
#pragma unroll
            for (int k = 1; k < 4; k++)
                if (ws[k] > best) { best = ws[k]; best_idx = k; }

            out[b * 2 + 0] = (float)(best_idx >> 1);  // row = idx // 2
            out[b * 2 + 1] = (float)(best_idx & 1);   // col = idx % 2
            g_count[b] = 0;                           // reset for graph replay
        }
    }
}

extern "C" void kernel_launch(void* const* d_in, const int* in_sizes, int n_in,
                              void* d_out, int out_size) {
    (void)in_sizes; (void)n_in; (void)out_size;
    const float* in = (const float*)d_in[0];
    float* out = (float*)d_out;
    region_selector_kernel<<<B * 16, 256>>>(in, out);
}

// round 12
// speedup vs baseline: 1.0472x; 1.0472x over previous
#include <cuda_runtime.h>
#include <cstdint>

// sampling_map: [B=64, C=3, H=512, W=512] fp32 row-major.
// GRID=4 -> 128x128 cells; channel-sum; valid 3x3 window over 4x4 grid -> 2x2;
// argmax (TOP_K=1) -> coords (idx//2, idx%2), output [B,1,2] as FLOAT32.
// Mean factor 1/16384 is uniform -> argmax-invariant -> dropped.
static constexpr int B = 64;
static constexpr int C = 3;
static constexpr int H = 512;
static constexpr int W = 512;
static constexpr int GH = 128;
static constexpr int GW = 128;
static constexpr int W4 = W / 4;       // 128 float4 per image row

// Device-global scratch (zero-init, allocation-guard safe).
__device__ float        g_cells[B * 16];
__device__ unsigned int g_count[B];

// Measured-optimal configuration (R9): one block per (batch, cell),
// 1024 x 256, residency capped at 4 CTAs/SM — cuts cross-CTA L1tex-queue
// contention and lets ptxas batch loads deeply (63 regs). Default __ldg
// caching beat both __ldcs and explicit MLP batching in A/B tests.
__global__ __launch_bounds__(256, 4) void region_selector_kernel(
    const float* __restrict__ in, float* __restrict__ out) {
    const int blk  = blockIdx.x;
    const int cell = blk & 15;
    const int b    = blk >> 4;
    const int gy   = cell >> 2;
    const int gx   = cell & 3;

    const int t     = threadIdx.x;
    const int lane8 = t & 7;    // 8 threads cover one 128-float row (4 float4 ea)
    const int r0    = t >> 3;   // base row 0..31

    float acc = 0.0f;
#pragma unroll
    for (int c = 0; c < C; c++) {
        const float4* __restrict__ base = reinterpret_cast<const float4*>(in) +
            (((size_t)(b * C + c) * H) + (size_t)gy * GH) * W4 + gx * (GW / 4);
#pragma unroll
        for (int m = 0; m < 4; m++) {
            const float4* __restrict__ rowp = base + (size_t)(r0 + m * 32) * W4;
#pragma unroll
            for (int j = 0; j < 4; j++) {
                float4 v = __ldg(&rowp[lane8 + j * 8]);
                acc += (v.x + v.y) + (v.z + v.w);
            }
        }
    }

    // Block reduction: warp shuffles, then 8 warps via smem.
    __shared__ float warp_sums[8];
#pragma unroll
    for (int off = 16; off > 0; off >>= 1)
        acc += __shfl_down_sync(0xFFFFFFFFu, acc, off);
    if ((t & 31) == 0) warp_sums[t >> 5] = acc;
    __syncthreads();

    if (t == 0) {
        float s = 0.0f;
#pragma unroll
        for (int w = 0; w < 8; w++) s += warp_sums[w];
        g_cells[blk] = s;
        __threadfence();                        // publish before the ticket
        const unsigned int done = atomicAdd(&g_count[b], 1u);
        if (done == 15u) {
            // Last finishing block of this batch: finalize.
            float cs[16];
#pragma unroll
            for (int k = 0; k < 16; k++)
                cs[k] = __ldcg(&g_cells[(b << 4) + k]);   // L2-coherent reads

            float ws[4];
#pragma unroll
            for (int i = 0; i < 2; i++) {
#pragma unroll
                for (int j = 0; j < 2; j++) {
                    float s2 = 0.0f;
#pragma unroll
                    for (int di = 0; di < 3; di++)
#pragma unroll
                        for (int dj = 0; dj < 3; dj++)
                            s2 += cs[(i + di) * 4 + (j + dj)];
                    ws[i * 2 + j] = s2;
                }
            }
            int best_idx = 0;
            float best = ws[0];
#pragma unroll
            for (int k = 1; k < 4; k++)
                if (ws[k] > best) { best = ws[k]; best_idx = k; }

            out[b * 2 + 0] = (float)(best_idx >> 1);  // row = idx // 2
            out[b * 2 + 1] = (float)(best_idx & 1);   // col = idx % 2
            g_count[b] = 0;                           // reset for graph replay
        }
    }
}

extern "C" void kernel_launch(void* const* d_in, const int* in_sizes, int n_in,
                              void* d_out, int out_size) {
    (void)in_sizes; (void)n_in; (void)out_size;
    const float* in = (const float*)d_in[0];
    float* out = (float*)d_out;
    region_selector_kernel<<<B * 16, 256>>>(in, out);
}